// round 15
// baseline (speedup 1.0000x reference)
#include <cuda_runtime.h>
#include <cuda_bf16.h>
#include <cstdint>

// ---------------- problem constants ----------------
#define NROWS   4096
#define MID     128
#define OUTDIM  5120
#define BROW    125
#define LN_EPSF 1e-5f

#define MTILES  (NROWS / 128)    // 32 row tiles
#define NOBLK   32               // o blocks (160 cols each)

// ---- smem layout (bytes) for gemm kernel (CTA tile 128 x 80) ----
#define OFF_A_HI   0            // 32768  (128 x 128 bf16, swizzled)
#define OFF_A_LO   32768        // 32768
#define OFF_B_HI   65536        // 20480  (80 x 128 bf16, swizzled)
#define OFF_B_LO   86016        // 20480   -> operands end 106496
// post-mainloop reuse:
#define OFF_STGC   0            // C staging: 128*81*4 = 41472
#define OFF_BASS   41472        // basis tile: 128*128*4 = 65536 (ends 107008)
#define OFF_B3     107008       // 80 f32 = 320
#define SMEM_TOTAL 107328       // ~104.8 KB -> 2 CTAs/SM
#define SPC        81           // C staging pitch (odd -> conflict-free)

// packed pre-swizzled operand images
__device__ __align__(16) __nv_bfloat16 g_Ahi[MTILES * 128 * 128];
__device__ __align__(16) __nv_bfloat16 g_Alo[MTILES * 128 * 128];
__device__ __align__(16) __nv_bfloat16 g_Bhi[NOBLK * 160 * 128];
__device__ __align__(16) __nv_bfloat16 g_Blo[NOBLK * 160 * 128];
// padded basis image: [rt][128 rows][128 j] (125 used)
__device__ __align__(16) float g_basP[MTILES * 128 * 128];

// ---------------- helpers ----------------
__device__ __forceinline__ uint32_t smem_u32(const void* p) {
    uint32_t a;
    asm("{ .reg .u64 t; cvta.to.shared.u64 t, %1; cvt.u32.u64 %0, t; }" : "=r"(a) : "l"(p));
    return a;
}
__device__ __forceinline__ void cp_async16(uint32_t dst, const void* src) {
    asm volatile("cp.async.cg.shared.global [%0], [%1], 16;" :: "r"(dst), "l"(src));
}
__device__ __forceinline__ void cp_commit() { asm volatile("cp.async.commit_group;"); }
template <int N> __device__ __forceinline__ void cp_wait() {
    asm volatile("cp.async.wait_group %0;" :: "n"(N));
}
__device__ __forceinline__ void ldmx4(uint32_t* r, uint32_t addr) {
    asm volatile("ldmatrix.sync.aligned.m8n8.x4.shared.b16 {%0,%1,%2,%3}, [%4];"
                 : "=r"(r[0]), "=r"(r[1]), "=r"(r[2]), "=r"(r[3]) : "r"(addr));
}
__device__ __forceinline__ void ldmx2(uint32_t* r, uint32_t addr) {
    asm volatile("ldmatrix.sync.aligned.m8n8.x2.shared.b16 {%0,%1}, [%2];"
                 : "=r"(r[0]), "=r"(r[1]) : "r"(addr));
}
__device__ __forceinline__ void mma16816(float* c, const uint32_t* a,
                                         uint32_t b0, uint32_t b1) {
    asm volatile(
        "mma.sync.aligned.m16n8k16.row.col.f32.bf16.bf16.f32 "
        "{%0,%1,%2,%3},{%4,%5,%6,%7},{%8,%9},{%0,%1,%2,%3};"
        : "+f"(c[0]), "+f"(c[1]), "+f"(c[2]), "+f"(c[3])
        : "r"(a[0]), "r"(a[1]), "r"(a[2]), "r"(a[3]), "r"(b0), "r"(b1));
}
// swizzled element index inside a [row][k=128] bf16 tile
__device__ __forceinline__ int swz_idx(int row, int k) {
    return row * 128 + ((((k >> 3) ^ (row & 7)) << 3) | (k & 7));
}

// =====================================================================
// Fused prep kernel, grid 416 x 256 threads:
//  [0,128)   packW3: (o = b>>2, nq = b&3) -> B hi/lo images
//  [128,160) basP:   pad basis to pitch-128 image
//  [160,416) stage12: 16 rows each (two 128-thread subgroups) -> A images
// =====================================================================
__global__ void __launch_bounds__(256) prep_kernel(
    const float* __restrict__ feat,  const float* __restrict__ basis,
    const float* __restrict__ W1, const float* __restrict__ b1,
    const float* __restrict__ g1, const float* __restrict__ be1,
    const float* __restrict__ W2, const float* __restrict__ b2,
    const float* __restrict__ g2, const float* __restrict__ be2,
    const float* __restrict__ W3)
{
    __shared__ __align__(16) char shraw[22528];
    const int b = blockIdx.x, t = threadIdx.x;

    if (b < 128) {
        // ---- packW3: o-block, n-quarter (40 cols) ----
        float* sw = (float*)shraw;                 // [128][41]
        const int o = b >> 2, nq = b & 3;
        for (int i = t; i < 128 * 40; i += 256) {
            int k = i / 40, nl = i - k * 40;
            sw[k * 41 + nl] = W3[(size_t)k * OUTDIM + o * 160 + nq * 40 + nl];
        }
        __syncthreads();
        uint32_t* bh = (uint32_t*)g_Bhi + o * 10240 + nq * 2560;
        uint32_t* bl = (uint32_t*)g_Blo + o * 10240 + nq * 2560;
        for (int li = t; li < 2560; li += 256) {
            int nl = li >> 6, wq = li & 63;
            int q = 2 * wq;
            int k = (((q >> 3) ^ (nl & 7)) << 3) | (q & 7);   // inverse swizzle
            float v0 = sw[k * 41 + nl];
            float v1 = sw[(k + 1) * 41 + nl];
            __nv_bfloat16 h0 = __float2bfloat16(v0), h1 = __float2bfloat16(v1);
            __nv_bfloat16 l0 = __float2bfloat16(v0 - __bfloat162float(h0));
            __nv_bfloat16 l1 = __float2bfloat16(v1 - __bfloat162float(h1));
            bh[li] = (uint32_t)__bfloat16_as_ushort(h0) |
                     ((uint32_t)__bfloat16_as_ushort(h1) << 16);
            bl[li] = (uint32_t)__bfloat16_as_ushort(l0) |
                     ((uint32_t)__bfloat16_as_ushort(l1) << 16);
        }
        return;
    }
    if (b < 160) {
        // ---- basP ----
        const int rt = b - 128;
        float* dst = g_basP + (size_t)rt * 16384;
        const float* src = basis + (size_t)rt * 128 * BROW;
        for (int i = t; i < 128 * BROW; i += 256) {
            int r = i / BROW, j = i - r * BROW;
            dst[r * 128 + j] = src[i];
        }
        return;
    }

    // ---- stage12 ----
    float* xs = (float*)shraw;                     // [2][8][128]
    float* rA = (float*)(shraw + 8192);            // [2][5][4]
    float* rB = (float*)(shraw + 8192 + 256);      // [2][8][2][4]
    const int b2i = b - 160;
    const int g  = t >> 7, tl = t & 127;
    const int w4 = tl >> 5, lane = t & 31;
    const int r0 = b2i * 16 + g * 8;
    const float invM = 1.0f / (float)MID;

    const float w = W1[tl], bb = b1[tl];
    float s0 = w, s1 = bb, s2 = w * w, s3 = w * bb, s4 = bb * bb;
    #pragma unroll
    for (int o = 16; o; o >>= 1) {
        s0 += __shfl_down_sync(0xffffffffu, s0, o);
        s1 += __shfl_down_sync(0xffffffffu, s1, o);
        s2 += __shfl_down_sync(0xffffffffu, s2, o);
        s3 += __shfl_down_sync(0xffffffffu, s3, o);
        s4 += __shfl_down_sync(0xffffffffu, s4, o);
    }
    if (!lane) {
        rA[(g * 5 + 0) * 4 + w4] = s0; rA[(g * 5 + 1) * 4 + w4] = s1;
        rA[(g * 5 + 2) * 4 + w4] = s2; rA[(g * 5 + 3) * 4 + w4] = s3;
        rA[(g * 5 + 4) * 4 + w4] = s4;
    }
    __syncthreads();
    float S[5];
    #pragma unroll
    for (int j = 0; j < 5; j++)
        S[j] = rA[(g * 5 + j) * 4 + 0] + rA[(g * 5 + j) * 4 + 1] +
               rA[(g * 5 + j) * 4 + 2] + rA[(g * 5 + j) * 4 + 3];

    const float gg = g1[tl], bg = be1[tl];
    #pragma unroll
    for (int r = 0; r < 8; r++) {
        float f   = feat[r0 + r];
        float mu  = (f * S[0] + S[1]) * invM;
        float e2  = (f * f * S[2] + 2.0f * f * S[3] + S[4]) * invM;
        float inv = rsqrtf(e2 - mu * mu + LN_EPSF);
        xs[(g * 8 + r) * 128 + tl] = fmaxf((f * w + bb - mu) * inv * gg + bg, 0.0f);
    }
    __syncthreads();

    float acc[8];
    #pragma unroll
    for (int r = 0; r < 8; r++) acc[r] = 0.0f;
    #pragma unroll 4
    for (int k = 0; k < MID; k++) {
        float wv = W2[k * MID + tl];
        #pragma unroll
        for (int r = 0; r < 8; r++) acc[r] = fmaf(xs[(g * 8 + r) * 128 + k], wv, acc[r]);
    }
    const float bv2 = b2[tl];
    #pragma unroll
    for (int r = 0; r < 8; r++) acc[r] += bv2;

    #pragma unroll
    for (int r = 0; r < 8; r++) {
        float v = acc[r], s = v, q = v * v;
        #pragma unroll
        for (int o = 16; o; o >>= 1) {
            s += __shfl_down_sync(0xffffffffu, s, o);
            q += __shfl_down_sync(0xffffffffu, q, o);
        }
        if (!lane) {
            rB[((g * 8 + r) * 2 + 0) * 4 + w4] = s;
            rB[((g * 8 + r) * 2 + 1) * 4 + w4] = q;
        }
    }
    __syncthreads();
    const float gv = g2[tl], bvx = be2[tl];
    #pragma unroll
    for (int r = 0; r < 8; r++) {
        float s = rB[((g * 8 + r) * 2 + 0) * 4 + 0] + rB[((g * 8 + r) * 2 + 0) * 4 + 1] +
                  rB[((g * 8 + r) * 2 + 0) * 4 + 2] + rB[((g * 8 + r) * 2 + 0) * 4 + 3];
        float q = rB[((g * 8 + r) * 2 + 1) * 4 + 0] + rB[((g * 8 + r) * 2 + 1) * 4 + 1] +
                  rB[((g * 8 + r) * 2 + 1) * 4 + 2] + rB[((g * 8 + r) * 2 + 1) * 4 + 3];
        float mu = s * invM;
        float inv = rsqrtf(q * invM - mu * mu + LN_EPSF);
        float v = fmaxf((acc[r] - mu) * inv * gv + bvx, 0.0f);
        int m = r0 + r;
        int tile = m >> 7, ml = m & 127;
        int idx = tile * 16384 + swz_idx(ml, tl);
        __nv_bfloat16 hh = __float2bfloat16(v);
        g_Ahi[idx] = hh;
        g_Alo[idx] = __float2bfloat16(v - __bfloat162float(hh));
    }
}

// =====================================================================
// GEMM (bf16x3 mma.sync, tile 128x80, 4m x 2n warp split)
// + float4 einsum epilogue (no shfl, all STG.128).
// grid (64, 32). 256 threads, 2 CTAs/SM.
// =====================================================================
__global__ void __launch_bounds__(256, 2)
gemm_einsum_mma(const float* __restrict__ b3,
                float* __restrict__ out)
{
    extern __shared__ __align__(16) char smem[];
    const uint32_t sb = smem_u32(smem);
    const int tid  = threadIdx.x;
    const int wid  = tid >> 5, lane = tid & 31;
    const int ob   = blockIdx.x >> 1;     // o block (0..31)
    const int h    = blockIdx.x & 1;      // column half (80 cols)
    const int rt   = blockIdx.y;          // row tile (0..31)
    const int r0   = rt * 128;

    // ---- cp.async: A hi/lo (64KB), B half hi/lo (40KB), b3 slice
    {
        const char* sAh = (const char*)(g_Ahi + (size_t)rt * 16384);
        const char* sAl = (const char*)(g_Alo + (size_t)rt * 16384);
        const char* sBh = (const char*)(g_Bhi + (size_t)ob * 20480 + h * 10240);
        const char* sBl = (const char*)(g_Blo + (size_t)ob * 20480 + h * 10240);
        for (int i = tid; i < 2048; i += 256) {
            cp_async16(sb + OFF_A_HI + i * 16, sAh + i * 16);
            cp_async16(sb + OFF_A_LO + i * 16, sAl + i * 16);
        }
        for (int i = tid; i < 1280; i += 256) {
            cp_async16(sb + OFF_B_HI + i * 16, sBh + i * 16);
            cp_async16(sb + OFF_B_LO + i * 16, sBl + i * 16);
        }
        const char* b3p = (const char*)(b3 + ob * 160 + h * 80);
        if (tid < 20) cp_async16(sb + OFF_B3 + tid * 16, b3p + tid * 16);
        cp_commit();
    }
    cp_wait<0>();
    __syncthreads();

    // ---- MMA mainloop: warp = (mg 0..3: 32 rows) x (wn 0..1: 40 B-rows) ----
    const int mg = wid >> 1;
    const int wn = wid & 1;
    const int axor = lane & 7;
    const int ak   = lane >> 4;
    const int bk   = (lane >> 3) & 1;

    const uint32_t aAddr  = sb + OFF_A_HI + ((mg * 32 + (lane & 15)) << 8);
    const uint32_t bAddr4 = sb + OFF_B_HI +
        ((wn * 40 + ((lane >> 4) & 1) * 8 + (lane & 7)) << 8);
    const uint32_t bAddr2 = sb + OFF_B_HI + ((wn * 40 + 32 + (lane & 7)) << 8);

    float c0[5][4], c1[5][4];
    #pragma unroll
    for (int n = 0; n < 5; n++)
        #pragma unroll
        for (int q = 0; q < 4; q++) { c0[n][q] = 0.0f; c1[n][q] = 0.0f; }

    #pragma unroll
    for (int kk = 0; kk < 8; kk++) {
        uint32_t gA = (uint32_t)(((2 * kk + ak) ^ axor) << 4);
        uint32_t gB = (uint32_t)(((2 * kk + bk) ^ axor) << 4);
        uint32_t ah0[4], al0[4], ah1[4], al1[4];
        ldmx4(ah0, aAddr + gA);
        ldmx4(al0, aAddr + 32768 + gA);
        ldmx4(ah1, aAddr + 4096 + gA);
        ldmx4(al1, aAddr + 4096 + 32768 + gA);
        #pragma unroll
        for (int j2 = 0; j2 < 2; j2++) {
            uint32_t bh[4], bl[4];
            uint32_t ba = bAddr4 + j2 * 4096 + gB;
            ldmx4(bh, ba);
            ldmx4(bl, ba + 20480);
            mma16816(c0[2 * j2], ah0, bh[0], bh[1]);
            mma16816(c0[2 * j2], ah0, bl[0], bl[1]);
            mma16816(c0[2 * j2], al0, bh[0], bh[1]);
            mma16816(c0[2 * j2 + 1], ah0, bh[2], bh[3]);
            mma16816(c0[2 * j2 + 1], ah0, bl[2], bl[3]);
            mma16816(c0[2 * j2 + 1], al0, bh[2], bh[3]);
            mma16816(c1[2 * j2], ah1, bh[0], bh[1]);
            mma16816(c1[2 * j2], ah1, bl[0], bl[1]);
            mma16816(c1[2 * j2], al1, bh[0], bh[1]);
            mma16816(c1[2 * j2 + 1], ah1, bh[2], bh[3]);
            mma16816(c1[2 * j2 + 1], ah1, bl[2], bl[3]);
            mma16816(c1[2 * j2 + 1], al1, bh[2], bh[3]);
        }
        {
            uint32_t bh2[2], bl2[2];
            ldmx2(bh2, bAddr2 + gB);
            ldmx2(bl2, bAddr2 + 20480 + gB);
            mma16816(c0[4], ah0, bh2[0], bh2[1]);
            mma16816(c0[4], ah0, bl2[0], bl2[1]);
            mma16816(c0[4], al0, bh2[0], bh2[1]);
            mma16816(c1[4], ah1, bh2[0], bh2[1]);
            mma16816(c1[4], ah1, bl2[0], bl2[1]);
            mma16816(c1[4], al1, bh2[0], bh2[1]);
        }
    }

    __syncthreads();   // all operand reads done; smem reusable

    // ---- kick basis cp.async into dead operand region (overlaps staging)
    {
        const char* bas = (const char*)(g_basP + (size_t)rt * 16384);
        for (int i = tid; i < 4096; i += 256)
            cp_async16(sb + OFF_BASS + i * 16, bas + i * 16);
        cp_commit();
    }

    // ---- stage C (+b3) to smem [128][SPC]
    float* stg = (float*)(smem + OFF_STGC);
    const float* sB3 = (const float*)(smem + OFF_B3);
    {
        const int rb = mg * 32 + (lane >> 2);
        #pragma unroll
        for (int mtl = 0; mtl < 2; mtl++) {
            int rlo = rb + mtl * 16;
            int rhi = rlo + 8;
            float (*cc)[4] = mtl ? c1 : c0;
            #pragma unroll
            for (int ntl = 0; ntl < 5; ntl++) {
                int col = wn * 40 + ntl * 8 + 2 * (lane & 3);
                float bA = sB3[col], bB = sB3[col + 1];
                stg[rlo * SPC + col]     = cc[ntl][0] + bA;
                stg[rlo * SPC + col + 1] = cc[ntl][1] + bB;
                stg[rhi * SPC + col]     = cc[ntl][2] + bA;
                stg[rhi * SPC + col + 1] = cc[ntl][3] + bB;
            }
        }
    }
    cp_wait<0>();        // basis landed
    __syncthreads();

    // ---- float4 einsum epilogue: warp owns rows wid*16..+15.
    // Lane owns (rr, q): 4 contiguous cols 4q..4q+3, loops d -> 5x STG.128.
    const float* bass = (const float*)(smem + OFF_BASS);

    #pragma unroll 1
    for (int pass = 0; pass < 10; pass++) {
        int idx  = pass * 32 + lane;          // 0..319
        int rr   = idx / 20;                  // 0..15
        int q    = idx - rr * 20;             // 0..19
        int rloc = wid * 16 + rr;
        int col0 = q * 4;

        int iu[4], mu[4];
        #pragma unroll
        for (int u = 0; u < 4; u++) {
            int c = col0 + u;
            iu[u] = c / 5;
            mu[u] = c - 5 * iu[u];
        }

        // R values for this lane's 4 columns (amortized over 5 d's)
        const float* Rrow = stg + rloc * SPC;
        float Rl[4][5];
        #pragma unroll
        for (int u = 0; u < 4; u++)
            #pragma unroll
            for (int f = 0; f < 5; f++)
                Rl[u][f] = Rrow[iu[u] * 5 + f];

        const float* basRow = bass + rloc * 128;
        float* outR = out + (size_t)(r0 + rloc) * 25600 + (size_t)ob * 800 +
                      h * 80 + col0;

        #pragma unroll
        for (int d = 0; d < 5; d++) {
            float vv[4];
            #pragma unroll
            for (int u = 0; u < 4; u++) {
                const float* bp = basRow + d * 25 + mu[u] * 5;
                float a = Rl[u][0] * bp[0];
                a = fmaf(Rl[u][1], bp[1], a);
                a = fmaf(Rl[u][2], bp[2], a);
                a = fmaf(Rl[u][3], bp[3], a);
                a = fmaf(Rl[u][4], bp[4], a);
                vv[u] = a;
            }
            float4 v; v.x = vv[0]; v.y = vv[1]; v.z = vv[2]; v.w = vv[3];
            *reinterpret_cast<float4*>(outR + d * 160) = v;
        }
    }
}

extern "C" void kernel_launch(void* const* d_in, const int* in_sizes, int n_in,
                              void* d_out, int out_size)
{
    const float* feat  = (const float*)d_in[0];
    const float* basis = (const float*)d_in[1];
    const float* W1    = (const float*)d_in[2];
    const float* b1    = (const float*)d_in[3];
    const float* g1    = (const float*)d_in[4];
    const float* be1   = (const float*)d_in[5];
    const float* W2    = (const float*)d_in[6];
    const float* b2    = (const float*)d_in[7];
    const float* g2    = (const float*)d_in[8];
    const float* be2   = (const float*)d_in[9];
    const float* W3    = (const float*)d_in[10];
    const float* b3    = (const float*)d_in[11];
    float* out = (float*)d_out;

    cudaFuncSetAttribute(gemm_einsum_mma,
                         cudaFuncAttributeMaxDynamicSharedMemorySize, SMEM_TOTAL);

    prep_kernel<<<416, 256>>>(feat, basis, W1, b1, g1, be1, W2, b2, g2, be2, W3);

    dim3 grid(NOBLK * 2, MTILES);   // (64, 32)
    gemm_einsum_mma<<<grid, 256, SMEM_TOTAL>>>(b3, out);
}

// round 16
// speedup vs baseline: 1.7390x; 1.7390x over previous
#include <cuda_runtime.h>
#include <cuda_bf16.h>
#include <cstdint>

// ---------------- problem constants ----------------
#define NROWS   4096
#define MID     128
#define OUTDIM  5120
#define BROW    125
#define LN_EPSF 1e-5f

#define MTILES  (NROWS / 128)    // 32 row tiles
#define NOBLK   32               // o blocks (160 cols each)

// ---- smem layout (bytes) for gemm kernel (CTA tile 128 x 80) ----
#define OFF_A_HI   0            // 32768  (128 x 128 bf16, swizzled)
#define OFF_A_LO   32768        // 32768
#define OFF_B_HI   65536        // 20480  (80 x 128 bf16, swizzled)
#define OFF_B_LO   86016        // 20480   -> operands end 106496
// post-mainloop reuse:
#define OFF_STGC   0            // C staging: 128*81*4 = 41472
#define OFF_BASS   41472        // basis tile: 128*128*4 = 65536 (ends 107008)
#define OFF_B3     107008       // 80 f32 = 320
#define SMEM_TOTAL 107328       // ~104.8 KB -> 2 CTAs/SM
#define SPC        81           // C staging pitch (odd -> conflict-free)

// packed pre-swizzled operand images
__device__ __align__(16) __nv_bfloat16 g_Ahi[MTILES * 128 * 128];
__device__ __align__(16) __nv_bfloat16 g_Alo[MTILES * 128 * 128];
__device__ __align__(16) __nv_bfloat16 g_Bhi[NOBLK * 160 * 128];
__device__ __align__(16) __nv_bfloat16 g_Blo[NOBLK * 160 * 128];
// permuted+padded basis image: [rt][128 rows][m*25 + d*5 + f] (pitch 128)
__device__ __align__(16) float g_basP[MTILES * 128 * 128];

// ---------------- helpers ----------------
__device__ __forceinline__ uint32_t smem_u32(const void* p) {
    uint32_t a;
    asm("{ .reg .u64 t; cvta.to.shared.u64 t, %1; cvt.u32.u64 %0, t; }" : "=r"(a) : "l"(p));
    return a;
}
__device__ __forceinline__ void cp_async16(uint32_t dst, const void* src) {
    asm volatile("cp.async.cg.shared.global [%0], [%1], 16;" :: "r"(dst), "l"(src));
}
__device__ __forceinline__ void cp_commit() { asm volatile("cp.async.commit_group;"); }
template <int N> __device__ __forceinline__ void cp_wait() {
    asm volatile("cp.async.wait_group %0;" :: "n"(N));
}
__device__ __forceinline__ void ldmx4(uint32_t* r, uint32_t addr) {
    asm volatile("ldmatrix.sync.aligned.m8n8.x4.shared.b16 {%0,%1,%2,%3}, [%4];"
                 : "=r"(r[0]), "=r"(r[1]), "=r"(r[2]), "=r"(r[3]) : "r"(addr));
}
__device__ __forceinline__ void ldmx2(uint32_t* r, uint32_t addr) {
    asm volatile("ldmatrix.sync.aligned.m8n8.x2.shared.b16 {%0,%1}, [%2];"
                 : "=r"(r[0]), "=r"(r[1]) : "r"(addr));
}
__device__ __forceinline__ void mma16816(float* c, const uint32_t* a,
                                         uint32_t b0, uint32_t b1) {
    asm volatile(
        "mma.sync.aligned.m16n8k16.row.col.f32.bf16.bf16.f32 "
        "{%0,%1,%2,%3},{%4,%5,%6,%7},{%8,%9},{%0,%1,%2,%3};"
        : "+f"(c[0]), "+f"(c[1]), "+f"(c[2]), "+f"(c[3])
        : "r"(a[0]), "r"(a[1]), "r"(a[2]), "r"(a[3]), "r"(b0), "r"(b1));
}
// swizzled element index inside a [row][k=128] bf16 tile
__device__ __forceinline__ int swz_idx(int row, int k) {
    return row * 128 + ((((k >> 3) ^ (row & 7)) << 3) | (k & 7));
}

// =====================================================================
// Fused prep kernel, grid 416 x 256 threads:
//  [0,128)   packW3: (o = b>>2, nq = b&3) -> B hi/lo images
//  [128,160) basP:   permute basis rows to [m][d][f], pitch-128 image
//  [160,416) stage12: 16 rows each (two 128-thread subgroups) -> A images
// =====================================================================
__global__ void __launch_bounds__(256) prep_kernel(
    const float* __restrict__ feat,  const float* __restrict__ basis,
    const float* __restrict__ W1, const float* __restrict__ b1,
    const float* __restrict__ g1, const float* __restrict__ be1,
    const float* __restrict__ W2, const float* __restrict__ b2,
    const float* __restrict__ g2, const float* __restrict__ be2,
    const float* __restrict__ W3)
{
    __shared__ __align__(16) char shraw[22528];
    const int b = blockIdx.x, t = threadIdx.x;

    if (b < 128) {
        // ---- packW3: o-block, n-quarter (40 cols) ----
        float* sw = (float*)shraw;                 // [128][41]
        const int o = b >> 2, nq = b & 3;
        for (int i = t; i < 128 * 40; i += 256) {
            int k = i / 40, nl = i - k * 40;
            sw[k * 41 + nl] = W3[(size_t)k * OUTDIM + o * 160 + nq * 40 + nl];
        }
        __syncthreads();
        uint32_t* bh = (uint32_t*)g_Bhi + o * 10240 + nq * 2560;
        uint32_t* bl = (uint32_t*)g_Blo + o * 10240 + nq * 2560;
        for (int li = t; li < 2560; li += 256) {
            int nl = li >> 6, wq = li & 63;
            int q = 2 * wq;
            int k = (((q >> 3) ^ (nl & 7)) << 3) | (q & 7);   // inverse swizzle
            float v0 = sw[k * 41 + nl];
            float v1 = sw[(k + 1) * 41 + nl];
            __nv_bfloat16 h0 = __float2bfloat16(v0), h1 = __float2bfloat16(v1);
            __nv_bfloat16 l0 = __float2bfloat16(v0 - __bfloat162float(h0));
            __nv_bfloat16 l1 = __float2bfloat16(v1 - __bfloat162float(h1));
            bh[li] = (uint32_t)__bfloat16_as_ushort(h0) |
                     ((uint32_t)__bfloat16_as_ushort(h1) << 16);
            bl[li] = (uint32_t)__bfloat16_as_ushort(l0) |
                     ((uint32_t)__bfloat16_as_ushort(l1) << 16);
        }
        return;
    }
    if (b < 160) {
        // ---- basP: permute [d][m][f] -> [m][d][f], pitch 128 ----
        const int rt = b - 128;
        float* dst = g_basP + (size_t)rt * 16384;
        const float* src = basis + (size_t)rt * 128 * BROW;
        for (int i = t; i < 128 * BROW; i += 256) {
            int r = i / BROW, j = i - r * BROW;     // j = m*25 + d*5 + f (dst order)
            int m = j / 25, rem = j - m * 25;
            int d = rem / 5, f = rem - d * 5;
            dst[r * 128 + j] = src[r * BROW + d * 25 + m * 5 + f];
        }
        return;
    }

    // ---- stage12 ----
    float* xs = (float*)shraw;                     // [2][8][128]
    float* rA = (float*)(shraw + 8192);            // [2][5][4]
    float* rB = (float*)(shraw + 8192 + 256);      // [2][8][2][4]
    const int b2i = b - 160;
    const int g  = t >> 7, tl = t & 127;
    const int w4 = tl >> 5, lane = t & 31;
    const int r0 = b2i * 16 + g * 8;
    const float invM = 1.0f / (float)MID;

    const float w = W1[tl], bb = b1[tl];
    float s0 = w, s1 = bb, s2 = w * w, s3 = w * bb, s4 = bb * bb;
    #pragma unroll
    for (int o = 16; o; o >>= 1) {
        s0 += __shfl_down_sync(0xffffffffu, s0, o);
        s1 += __shfl_down_sync(0xffffffffu, s1, o);
        s2 += __shfl_down_sync(0xffffffffu, s2, o);
        s3 += __shfl_down_sync(0xffffffffu, s3, o);
        s4 += __shfl_down_sync(0xffffffffu, s4, o);
    }
    if (!lane) {
        rA[(g * 5 + 0) * 4 + w4] = s0; rA[(g * 5 + 1) * 4 + w4] = s1;
        rA[(g * 5 + 2) * 4 + w4] = s2; rA[(g * 5 + 3) * 4 + w4] = s3;
        rA[(g * 5 + 4) * 4 + w4] = s4;
    }
    __syncthreads();
    float S[5];
    #pragma unroll
    for (int j = 0; j < 5; j++)
        S[j] = rA[(g * 5 + j) * 4 + 0] + rA[(g * 5 + j) * 4 + 1] +
               rA[(g * 5 + j) * 4 + 2] + rA[(g * 5 + j) * 4 + 3];

    const float gg = g1[tl], bg = be1[tl];
    #pragma unroll
    for (int r = 0; r < 8; r++) {
        float f   = feat[r0 + r];
        float mu  = (f * S[0] + S[1]) * invM;
        float e2  = (f * f * S[2] + 2.0f * f * S[3] + S[4]) * invM;
        float inv = rsqrtf(e2 - mu * mu + LN_EPSF);
        xs[(g * 8 + r) * 128 + tl] = fmaxf((f * w + bb - mu) * inv * gg + bg, 0.0f);
    }
    __syncthreads();

    float acc[8];
    #pragma unroll
    for (int r = 0; r < 8; r++) acc[r] = 0.0f;
    #pragma unroll 4
    for (int k = 0; k < MID; k++) {
        float wv = W2[k * MID + tl];
        #pragma unroll
        for (int r = 0; r < 8; r++) acc[r] = fmaf(xs[(g * 8 + r) * 128 + k], wv, acc[r]);
    }
    const float bv2 = b2[tl];
    #pragma unroll
    for (int r = 0; r < 8; r++) acc[r] += bv2;

    #pragma unroll
    for (int r = 0; r < 8; r++) {
        float v = acc[r], s = v, q = v * v;
        #pragma unroll
        for (int o = 16; o; o >>= 1) {
            s += __shfl_down_sync(0xffffffffu, s, o);
            q += __shfl_down_sync(0xffffffffu, q, o);
        }
        if (!lane) {
            rB[((g * 8 + r) * 2 + 0) * 4 + w4] = s;
            rB[((g * 8 + r) * 2 + 1) * 4 + w4] = q;
        }
    }
    __syncthreads();
    const float gv = g2[tl], bvx = be2[tl];
    #pragma unroll
    for (int r = 0; r < 8; r++) {
        float s = rB[((g * 8 + r) * 2 + 0) * 4 + 0] + rB[((g * 8 + r) * 2 + 0) * 4 + 1] +
                  rB[((g * 8 + r) * 2 + 0) * 4 + 2] + rB[((g * 8 + r) * 2 + 0) * 4 + 3];
        float q = rB[((g * 8 + r) * 2 + 1) * 4 + 0] + rB[((g * 8 + r) * 2 + 1) * 4 + 1] +
                  rB[((g * 8 + r) * 2 + 1) * 4 + 2] + rB[((g * 8 + r) * 2 + 1) * 4 + 3];
        float mu = s * invM;
        float inv = rsqrtf(q * invM - mu * mu + LN_EPSF);
        float v = fmaxf((acc[r] - mu) * inv * gv + bvx, 0.0f);
        int m = r0 + r;
        int tile = m >> 7, ml = m & 127;
        int idx = tile * 16384 + swz_idx(ml, tl);
        __nv_bfloat16 hh = __float2bfloat16(v);
        g_Ahi[idx] = hh;
        g_Alo[idx] = __float2bfloat16(v - __bfloat162float(hh));
    }
}

// =====================================================================
// GEMM (bf16x3 mma.sync, tile 128x80, 4m x 2n warp split)
// + shfl-free warp-per-row einsum epilogue.
// grid (64, 32). 256 threads, 2 CTAs/SM.
// =====================================================================
__global__ void __launch_bounds__(256, 2)
gemm_einsum_mma(const float* __restrict__ b3,
                float* __restrict__ out)
{
    extern __shared__ __align__(16) char smem[];
    const uint32_t sb = smem_u32(smem);
    const int tid  = threadIdx.x;
    const int wid  = tid >> 5, lane = tid & 31;
    const int ob   = blockIdx.x >> 1;     // o block (0..31)
    const int h    = blockIdx.x & 1;      // column half (80 cols)
    const int rt   = blockIdx.y;          // row tile (0..31)
    const int r0   = rt * 128;

    // ---- cp.async: A hi/lo (64KB), B half hi/lo (40KB), b3 slice
    {
        const char* sAh = (const char*)(g_Ahi + (size_t)rt * 16384);
        const char* sAl = (const char*)(g_Alo + (size_t)rt * 16384);
        const char* sBh = (const char*)(g_Bhi + (size_t)ob * 20480 + h * 10240);
        const char* sBl = (const char*)(g_Blo + (size_t)ob * 20480 + h * 10240);
        for (int i = tid; i < 2048; i += 256) {
            cp_async16(sb + OFF_A_HI + i * 16, sAh + i * 16);
            cp_async16(sb + OFF_A_LO + i * 16, sAl + i * 16);
        }
        for (int i = tid; i < 1280; i += 256) {
            cp_async16(sb + OFF_B_HI + i * 16, sBh + i * 16);
            cp_async16(sb + OFF_B_LO + i * 16, sBl + i * 16);
        }
        const char* b3p = (const char*)(b3 + ob * 160 + h * 80);
        if (tid < 20) cp_async16(sb + OFF_B3 + tid * 16, b3p + tid * 16);
        cp_commit();
    }
    cp_wait<0>();
    __syncthreads();

    // ---- MMA mainloop: warp = (mg 0..3: 32 rows) x (wn 0..1: 40 B-rows) ----
    const int mg = wid >> 1;
    const int wn = wid & 1;
    const int axor = lane & 7;
    const int ak   = lane >> 4;
    const int bk   = (lane >> 3) & 1;

    const uint32_t aAddr  = sb + OFF_A_HI + ((mg * 32 + (lane & 15)) << 8);
    const uint32_t bAddr4 = sb + OFF_B_HI +
        ((wn * 40 + ((lane >> 4) & 1) * 8 + (lane & 7)) << 8);
    const uint32_t bAddr2 = sb + OFF_B_HI + ((wn * 40 + 32 + (lane & 7)) << 8);

    float c0[5][4], c1[5][4];
    #pragma unroll
    for (int n = 0; n < 5; n++)
        #pragma unroll
        for (int q = 0; q < 4; q++) { c0[n][q] = 0.0f; c1[n][q] = 0.0f; }

    #pragma unroll
    for (int kk = 0; kk < 8; kk++) {
        uint32_t gA = (uint32_t)(((2 * kk + ak) ^ axor) << 4);
        uint32_t gB = (uint32_t)(((2 * kk + bk) ^ axor) << 4);
        uint32_t ah0[4], al0[4], ah1[4], al1[4];
        ldmx4(ah0, aAddr + gA);
        ldmx4(al0, aAddr + 32768 + gA);
        ldmx4(ah1, aAddr + 4096 + gA);
        ldmx4(al1, aAddr + 4096 + 32768 + gA);
        #pragma unroll
        for (int j2 = 0; j2 < 2; j2++) {
            uint32_t bh[4], bl[4];
            uint32_t ba = bAddr4 + j2 * 4096 + gB;
            ldmx4(bh, ba);
            ldmx4(bl, ba + 20480);
            mma16816(c0[2 * j2], ah0, bh[0], bh[1]);
            mma16816(c0[2 * j2], ah0, bl[0], bl[1]);
            mma16816(c0[2 * j2], al0, bh[0], bh[1]);
            mma16816(c0[2 * j2 + 1], ah0, bh[2], bh[3]);
            mma16816(c0[2 * j2 + 1], ah0, bl[2], bl[3]);
            mma16816(c0[2 * j2 + 1], al0, bh[2], bh[3]);
            mma16816(c1[2 * j2], ah1, bh[0], bh[1]);
            mma16816(c1[2 * j2], ah1, bl[0], bl[1]);
            mma16816(c1[2 * j2], al1, bh[0], bh[1]);
            mma16816(c1[2 * j2 + 1], ah1, bh[2], bh[3]);
            mma16816(c1[2 * j2 + 1], ah1, bl[2], bl[3]);
            mma16816(c1[2 * j2 + 1], al1, bh[2], bh[3]);
        }
        {
            uint32_t bh2[2], bl2[2];
            ldmx2(bh2, bAddr2 + gB);
            ldmx2(bl2, bAddr2 + 20480 + gB);
            mma16816(c0[4], ah0, bh2[0], bh2[1]);
            mma16816(c0[4], ah0, bl2[0], bl2[1]);
            mma16816(c0[4], al0, bh2[0], bh2[1]);
            mma16816(c1[4], ah1, bh2[0], bh2[1]);
            mma16816(c1[4], ah1, bl2[0], bl2[1]);
            mma16816(c1[4], al1, bh2[0], bh2[1]);
        }
    }

    __syncthreads();   // all operand reads done; smem reusable

    // ---- kick basis cp.async into dead operand region (overlaps staging)
    {
        const char* bas = (const char*)(g_basP + (size_t)rt * 16384);
        for (int i = tid; i < 4096; i += 256)
            cp_async16(sb + OFF_BASS + i * 16, bas + i * 16);
        cp_commit();
    }

    // ---- stage C (+b3) to smem [128][SPC]
    float* stg = (float*)(smem + OFF_STGC);
    const float* sB3 = (const float*)(smem + OFF_B3);
    {
        const int rb = mg * 32 + (lane >> 2);
        #pragma unroll
        for (int mtl = 0; mtl < 2; mtl++) {
            int rlo = rb + mtl * 16;
            int rhi = rlo + 8;
            float (*cc)[4] = mtl ? c1 : c0;
            #pragma unroll
            for (int ntl = 0; ntl < 5; ntl++) {
                int col = wn * 40 + ntl * 8 + 2 * (lane & 3);
                float bA = sB3[col], bB = sB3[col + 1];
                stg[rlo * SPC + col]     = cc[ntl][0] + bA;
                stg[rlo * SPC + col + 1] = cc[ntl][1] + bB;
                stg[rhi * SPC + col]     = cc[ntl][2] + bA;
                stg[rhi * SPC + col + 1] = cc[ntl][3] + bB;
            }
        }
    }
    cp_wait<0>();        // basis landed
    __syncthreads();

    // ---- shfl-free warp-per-row einsum epilogue.
    // Lane = (il, ml) = (lane/5, lane%5). Pass p covers cols p*30 + lane.
    // Basis image is [row][ml*25 + d*5 + f] so each lane's 25 values are
    // loaded once per row (conflict-free) and reused across passes.
    const float* bass = (const float*)(smem + OFF_BASS);
    const int ml = lane % 5;
    const int act01 = (lane < 30);
    const int act2  = (lane < 20);

    #pragma unroll 1
    for (int rr = 0; rr < 16; rr++) {
        const int rloc = wid * 16 + rr;
        const float* Rrow   = stg + rloc * SPC;
        const float* basRow = bass + rloc * 128 + ml * 25;

        float bw[25];
        #pragma unroll
        for (int j = 0; j < 25; j++) bw[j] = basRow[j];

        float* outR = out + (size_t)(r0 + rloc) * 25600 + (size_t)ob * 800 + h * 80;

        #pragma unroll
        for (int p = 0; p < 3; p++) {
            int col = p * 30 + lane;              // output column
            int act = (p < 2) ? act01 : act2;
            int i5  = (col < 80 ? col - ml : 0);  // i*5 (guard for idle lanes)
            float Rf[5];
            #pragma unroll
            for (int f = 0; f < 5; f++) Rf[f] = Rrow[i5 + f];
            #pragma unroll
            for (int d = 0; d < 5; d++) {
                float a = Rf[0] * bw[d * 5];
                a = fmaf(Rf[1], bw[d * 5 + 1], a);
                a = fmaf(Rf[2], bw[d * 5 + 2], a);
                a = fmaf(Rf[3], bw[d * 5 + 3], a);
                a = fmaf(Rf[4], bw[d * 5 + 4], a);
                if (act) outR[d * 160 + col] = a;
            }
        }
    }
}

extern "C" void kernel_launch(void* const* d_in, const int* in_sizes, int n_in,
                              void* d_out, int out_size)
{
    const float* feat  = (const float*)d_in[0];
    const float* basis = (const float*)d_in[1];
    const float* W1    = (const float*)d_in[2];
    const float* b1    = (const float*)d_in[3];
    const float* g1    = (const float*)d_in[4];
    const float* be1   = (const float*)d_in[5];
    const float* W2    = (const float*)d_in[6];
    const float* b2    = (const float*)d_in[7];
    const float* g2    = (const float*)d_in[8];
    const float* be2   = (const float*)d_in[9];
    const float* W3    = (const float*)d_in[10];
    const float* b3    = (const float*)d_in[11];
    float* out = (float*)d_out;

    cudaFuncSetAttribute(gemm_einsum_mma,
                         cudaFuncAttributeMaxDynamicSharedMemorySize, SMEM_TOTAL);

    prep_kernel<<<416, 256>>>(feat, basis, W1, b1, g1, be1, W2, b2, g2, be2, W3);

    dim3 grid(NOBLK * 2, MTILES);   // (64, 32)
    gemm_einsum_mma<<<grid, 256, SMEM_TOTAL>>>(b3, out);
}

// round 17
// speedup vs baseline: 1.7621x; 1.0133x over previous
#include <cuda_runtime.h>
#include <cuda_bf16.h>
#include <cstdint>

// ---------------- problem constants ----------------
#define NROWS   4096
#define MID     128
#define OUTDIM  5120
#define BROW    125
#define LN_EPSF 1e-5f

#define MTILES  (NROWS / 128)    // 32 row tiles
#define NOBLK   32               // o blocks (160 cols each)

// ---- smem layout (bytes) for gemm kernel (CTA tile 128 x 80) ----
#define OFF_A_HI   0            // 32768  (128 x 128 bf16, swizzled)
#define OFF_A_LO   32768        // 32768
#define OFF_B_HI   65536        // 20480  (80 x 128 bf16, swizzled)
#define OFF_B_LO   86016        // 20480   -> operands end 106496
// post-mainloop reuse:
#define OFF_STGC   0            // C staging: 128*81*4 = 41472
#define OFF_BASS   41472        // basis tile: 128*140*4 = 71680 (ends 113152)
#define OFF_B3     113152       // 80 f32 = 320 (outside operands AND BASS)
#define SMEM_TOTAL 113472       // -> 2 CTAs/SM (226944 <= 228KB)
#define SPC        81           // C staging pitch (odd -> conflict-free)
#define BPITCH     140          // basis row pitch (floats); m-stride 28

// packed pre-swizzled operand images
__device__ __align__(16) __nv_bfloat16 g_Ahi[MTILES * 128 * 128];
__device__ __align__(16) __nv_bfloat16 g_Alo[MTILES * 128 * 128];
__device__ __align__(16) __nv_bfloat16 g_Bhi[NOBLK * 160 * 128];
__device__ __align__(16) __nv_bfloat16 g_Blo[NOBLK * 160 * 128];
// permuted+padded basis image: [rt][128 rows][m*28 + d*5 + f] (pitch 140)
__device__ __align__(16) float g_basP[MTILES * 128 * BPITCH];

// ---------------- helpers ----------------
__device__ __forceinline__ uint32_t smem_u32(const void* p) {
    uint32_t a;
    asm("{ .reg .u64 t; cvta.to.shared.u64 t, %1; cvt.u32.u64 %0, t; }" : "=r"(a) : "l"(p));
    return a;
}
__device__ __forceinline__ void cp_async16(uint32_t dst, const void* src) {
    asm volatile("cp.async.cg.shared.global [%0], [%1], 16;" :: "r"(dst), "l"(src));
}
__device__ __forceinline__ void cp_commit() { asm volatile("cp.async.commit_group;"); }
template <int N> __device__ __forceinline__ void cp_wait() {
    asm volatile("cp.async.wait_group %0;" :: "n"(N));
}
__device__ __forceinline__ void ldmx4(uint32_t* r, uint32_t addr) {
    asm volatile("ldmatrix.sync.aligned.m8n8.x4.shared.b16 {%0,%1,%2,%3}, [%4];"
                 : "=r"(r[0]), "=r"(r[1]), "=r"(r[2]), "=r"(r[3]) : "r"(addr));
}
__device__ __forceinline__ void ldmx2(uint32_t* r, uint32_t addr) {
    asm volatile("ldmatrix.sync.aligned.m8n8.x2.shared.b16 {%0,%1}, [%2];"
                 : "=r"(r[0]), "=r"(r[1]) : "r"(addr));
}
__device__ __forceinline__ void mma16816(float* c, const uint32_t* a,
                                         uint32_t b0, uint32_t b1) {
    asm volatile(
        "mma.sync.aligned.m16n8k16.row.col.f32.bf16.bf16.f32 "
        "{%0,%1,%2,%3},{%4,%5,%6,%7},{%8,%9},{%0,%1,%2,%3};"
        : "+f"(c[0]), "+f"(c[1]), "+f"(c[2]), "+f"(c[3])
        : "r"(a[0]), "r"(a[1]), "r"(a[2]), "r"(a[3]), "r"(b0), "r"(b1));
}
// swizzled element index inside a [row][k=128] bf16 tile
__device__ __forceinline__ int swz_idx(int row, int k) {
    return row * 128 + ((((k >> 3) ^ (row & 7)) << 3) | (k & 7));
}

// =====================================================================
// Fused prep kernel, grid 416 x 256 threads:
//  [0,128)   packW3: (o = b>>2, nq = b&3) -> B hi/lo images
//  [128,160) basP:   permute basis rows to [m][d][f] w/ m-stride 28
//  [160,416) stage12: 16 rows each (two 128-thread subgroups) -> A images
// =====================================================================
__global__ void __launch_bounds__(256) prep_kernel(
    const float* __restrict__ feat,  const float* __restrict__ basis,
    const float* __restrict__ W1, const float* __restrict__ b1,
    const float* __restrict__ g1, const float* __restrict__ be1,
    const float* __restrict__ W2, const float* __restrict__ b2,
    const float* __restrict__ g2, const float* __restrict__ be2,
    const float* __restrict__ W3)
{
    __shared__ __align__(16) char shraw[22528];
    const int b = blockIdx.x, t = threadIdx.x;

    if (b < 128) {
        // ---- packW3: o-block, n-quarter (40 cols) ----
        float* sw = (float*)shraw;                 // [128][41]
        const int o = b >> 2, nq = b & 3;
        for (int i = t; i < 128 * 40; i += 256) {
            int k = i / 40, nl = i - k * 40;
            sw[k * 41 + nl] = W3[(size_t)k * OUTDIM + o * 160 + nq * 40 + nl];
        }
        __syncthreads();
        uint32_t* bh = (uint32_t*)g_Bhi + o * 10240 + nq * 2560;
        uint32_t* bl = (uint32_t*)g_Blo + o * 10240 + nq * 2560;
        for (int li = t; li < 2560; li += 256) {
            int nl = li >> 6, wq = li & 63;
            int q = 2 * wq;
            int k = (((q >> 3) ^ (nl & 7)) << 3) | (q & 7);   // inverse swizzle
            float v0 = sw[k * 41 + nl];
            float v1 = sw[(k + 1) * 41 + nl];
            __nv_bfloat16 h0 = __float2bfloat16(v0), h1 = __float2bfloat16(v1);
            __nv_bfloat16 l0 = __float2bfloat16(v0 - __bfloat162float(h0));
            __nv_bfloat16 l1 = __float2bfloat16(v1 - __bfloat162float(h1));
            bh[li] = (uint32_t)__bfloat16_as_ushort(h0) |
                     ((uint32_t)__bfloat16_as_ushort(h1) << 16);
            bl[li] = (uint32_t)__bfloat16_as_ushort(l0) |
                     ((uint32_t)__bfloat16_as_ushort(l1) << 16);
        }
        return;
    }
    if (b < 160) {
        // ---- basP: permute [d][m][f] -> [m][d][f], m-stride 28, pitch 140 ----
        const int rt = b - 128;
        float* dst = g_basP + (size_t)rt * 128 * BPITCH;
        const float* src = basis + (size_t)rt * 128 * BROW;
        // zero-fill pad lanes (so cp.async image is fully initialized)
        for (int i = t; i < 128 * BPITCH; i += 256) dst[i] = 0.0f;
        __syncthreads();
        for (int i = t; i < 128 * BROW; i += 256) {
            int r = i / BROW, j = i - r * BROW;     // j = m*25 + d*5 + f (logical)
            int m = j / 25, rem = j - m * 25;
            int d = rem / 5, f = rem - d * 5;
            dst[r * BPITCH + m * 28 + d * 5 + f] = src[r * BROW + d * 25 + m * 5 + f];
        }
        return;
    }

    // ---- stage12 ----
    float* xs = (float*)shraw;                     // [2][8][128]
    float* rA = (float*)(shraw + 8192);            // [2][5][4]
    float* rB = (float*)(shraw + 8192 + 256);      // [2][8][2][4]
    const int b2i = b - 160;
    const int g  = t >> 7, tl = t & 127;
    const int w4 = tl >> 5, lane = t & 31;
    const int r0 = b2i * 16 + g * 8;
    const float invM = 1.0f / (float)MID;

    const float w = W1[tl], bb = b1[tl];
    float s0 = w, s1 = bb, s2 = w * w, s3 = w * bb, s4 = bb * bb;
    #pragma unroll
    for (int o = 16; o; o >>= 1) {
        s0 += __shfl_down_sync(0xffffffffu, s0, o);
        s1 += __shfl_down_sync(0xffffffffu, s1, o);
        s2 += __shfl_down_sync(0xffffffffu, s2, o);
        s3 += __shfl_down_sync(0xffffffffu, s3, o);
        s4 += __shfl_down_sync(0xffffffffu, s4, o);
    }
    if (!lane) {
        rA[(g * 5 + 0) * 4 + w4] = s0; rA[(g * 5 + 1) * 4 + w4] = s1;
        rA[(g * 5 + 2) * 4 + w4] = s2; rA[(g * 5 + 3) * 4 + w4] = s3;
        rA[(g * 5 + 4) * 4 + w4] = s4;
    }
    __syncthreads();
    float S[5];
    #pragma unroll
    for (int j = 0; j < 5; j++)
        S[j] = rA[(g * 5 + j) * 4 + 0] + rA[(g * 5 + j) * 4 + 1] +
               rA[(g * 5 + j) * 4 + 2] + rA[(g * 5 + j) * 4 + 3];

    const float gg = g1[tl], bg = be1[tl];
    #pragma unroll
    for (int r = 0; r < 8; r++) {
        float f   = feat[r0 + r];
        float mu  = (f * S[0] + S[1]) * invM;
        float e2  = (f * f * S[2] + 2.0f * f * S[3] + S[4]) * invM;
        float inv = rsqrtf(e2 - mu * mu + LN_EPSF);
        xs[(g * 8 + r) * 128 + tl] = fmaxf((f * w + bb - mu) * inv * gg + bg, 0.0f);
    }
    __syncthreads();

    float acc[8];
    #pragma unroll
    for (int r = 0; r < 8; r++) acc[r] = 0.0f;
    #pragma unroll 4
    for (int k = 0; k < MID; k++) {
        float wv = W2[k * MID + tl];
        #pragma unroll
        for (int r = 0; r < 8; r++) acc[r] = fmaf(xs[(g * 8 + r) * 128 + k], wv, acc[r]);
    }
    const float bv2 = b2[tl];
    #pragma unroll
    for (int r = 0; r < 8; r++) acc[r] += bv2;

    #pragma unroll
    for (int r = 0; r < 8; r++) {
        float v = acc[r], s = v, q = v * v;
        #pragma unroll
        for (int o = 16; o; o >>= 1) {
            s += __shfl_down_sync(0xffffffffu, s, o);
            q += __shfl_down_sync(0xffffffffu, q, o);
        }
        if (!lane) {
            rB[((g * 8 + r) * 2 + 0) * 4 + w4] = s;
            rB[((g * 8 + r) * 2 + 1) * 4 + w4] = q;
        }
    }
    __syncthreads();
    const float gv = g2[tl], bvx = be2[tl];
    #pragma unroll
    for (int r = 0; r < 8; r++) {
        float s = rB[((g * 8 + r) * 2 + 0) * 4 + 0] + rB[((g * 8 + r) * 2 + 0) * 4 + 1] +
                  rB[((g * 8 + r) * 2 + 0) * 4 + 2] + rB[((g * 8 + r) * 2 + 0) * 4 + 3];
        float q = rB[((g * 8 + r) * 2 + 1) * 4 + 0] + rB[((g * 8 + r) * 2 + 1) * 4 + 1] +
                  rB[((g * 8 + r) * 2 + 1) * 4 + 2] + rB[((g * 8 + r) * 2 + 1) * 4 + 3];
        float mu = s * invM;
        float inv = rsqrtf(q * invM - mu * mu + LN_EPSF);
        float v = fmaxf((acc[r] - mu) * inv * gv + bvx, 0.0f);
        int m = r0 + r;
        int tile = m >> 7, ml = m & 127;
        int idx = tile * 16384 + swz_idx(ml, tl);
        __nv_bfloat16 hh = __float2bfloat16(v);
        g_Ahi[idx] = hh;
        g_Alo[idx] = __float2bfloat16(v - __bfloat162float(hh));
    }
}

// =====================================================================
// GEMM (bf16x3 mma.sync, tile 128x80, 4m x 2n warp split, k-split pipe)
// + shfl-free warp-per-row einsum epilogue (float4 basis loads).
// grid (64, 32). 256 threads, 2 CTAs/SM.
// =====================================================================
__global__ void __launch_bounds__(256, 2)
gemm_einsum_mma(const float* __restrict__ b3,
                float* __restrict__ out)
{
    extern __shared__ __align__(16) char smem[];
    const uint32_t sb = smem_u32(smem);
    const int tid  = threadIdx.x;
    const int wid  = tid >> 5, lane = tid & 31;
    const int ob   = blockIdx.x >> 1;     // o block (0..31)
    const int h    = blockIdx.x & 1;      // column half (80 cols)
    const int rt   = blockIdx.y;          // row tile (0..31)
    const int r0   = rt * 128;

    // ---- cp.async in 3 groups: khalf0 (A+B), khalf1 (A+B), b3
    {
        const char* sAh = (const char*)(g_Ahi + (size_t)rt * 16384);
        const char* sAl = (const char*)(g_Alo + (size_t)rt * 16384);
        const char* sBh = (const char*)(g_Bhi + (size_t)ob * 20480 + h * 10240);
        const char* sBl = (const char*)(g_Blo + (size_t)ob * 20480 + h * 10240);
        // group 0: k 0..63 -> granule (i&7) of each 16-granule row
        for (int i = tid; i < 1024; i += 256) {
            int gi = ((i >> 3) << 4) + (i & 7);       // row*16 + g (g<8)
            cp_async16(sb + OFF_A_HI + gi * 16, sAh + gi * 16);
            cp_async16(sb + OFF_A_LO + gi * 16, sAl + gi * 16);
        }
        for (int i = tid; i < 640; i += 256) {
            int gi = ((i >> 3) << 4) + (i & 7);
            cp_async16(sb + OFF_B_HI + gi * 16, sBh + gi * 16);
            cp_async16(sb + OFF_B_LO + gi * 16, sBl + gi * 16);
        }
        cp_commit();
        // group 1: k 64..127
        for (int i = tid; i < 1024; i += 256) {
            int gi = ((i >> 3) << 4) + (i & 7) + 8;
            cp_async16(sb + OFF_A_HI + gi * 16, sAh + gi * 16);
            cp_async16(sb + OFF_A_LO + gi * 16, sAl + gi * 16);
        }
        for (int i = tid; i < 640; i += 256) {
            int gi = ((i >> 3) << 4) + (i & 7) + 8;
            cp_async16(sb + OFF_B_HI + gi * 16, sBh + gi * 16);
            cp_async16(sb + OFF_B_LO + gi * 16, sBl + gi * 16);
        }
        cp_commit();
        // group 2: b3 slice
        const char* b3p = (const char*)(b3 + ob * 160 + h * 80);
        if (tid < 20) cp_async16(sb + OFF_B3 + tid * 16, b3p + tid * 16);
        cp_commit();
    }

    // ---- MMA mainloop: warp = (mg 0..3: 32 rows) x (wn 0..1: 40 B-rows) ----
    const int mg = wid >> 1;
    const int wn = wid & 1;
    const int axor = lane & 7;
    const int ak   = lane >> 4;
    const int bk   = (lane >> 3) & 1;

    const uint32_t aAddr  = sb + OFF_A_HI + ((mg * 32 + (lane & 15)) << 8);
    const uint32_t bAddr4 = sb + OFF_B_HI +
        ((wn * 40 + ((lane >> 4) & 1) * 8 + (lane & 7)) << 8);
    const uint32_t bAddr2 = sb + OFF_B_HI + ((wn * 40 + 32 + (lane & 7)) << 8);

    float c0[5][4], c1[5][4];
    #pragma unroll
    for (int n = 0; n < 5; n++)
        #pragma unroll
        for (int q = 0; q < 4; q++) { c0[n][q] = 0.0f; c1[n][q] = 0.0f; }

    #pragma unroll 1
    for (int hk = 0; hk < 2; hk++) {
        if (hk == 0) cp_wait<2>(); else cp_wait<1>();
        __syncthreads();
        #pragma unroll
        for (int k4 = 0; k4 < 4; k4++) {
            int kk = hk * 4 + k4;
            uint32_t gA = (uint32_t)(((2 * kk + ak) ^ axor) << 4);
            uint32_t gB = (uint32_t)(((2 * kk + bk) ^ axor) << 4);
            uint32_t ah0[4], al0[4], ah1[4], al1[4];
            ldmx4(ah0, aAddr + gA);
            ldmx4(al0, aAddr + 32768 + gA);
            ldmx4(ah1, aAddr + 4096 + gA);
            ldmx4(al1, aAddr + 4096 + 32768 + gA);
            #pragma unroll
            for (int j2 = 0; j2 < 2; j2++) {
                uint32_t bh[4], bl[4];
                uint32_t ba = bAddr4 + j2 * 4096 + gB;
                ldmx4(bh, ba);
                ldmx4(bl, ba + 20480);
                mma16816(c0[2 * j2], ah0, bh[0], bh[1]);
                mma16816(c0[2 * j2], ah0, bl[0], bl[1]);
                mma16816(c0[2 * j2], al0, bh[0], bh[1]);
                mma16816(c0[2 * j2 + 1], ah0, bh[2], bh[3]);
                mma16816(c0[2 * j2 + 1], ah0, bl[2], bl[3]);
                mma16816(c0[2 * j2 + 1], al0, bh[2], bh[3]);
                mma16816(c1[2 * j2], ah1, bh[0], bh[1]);
                mma16816(c1[2 * j2], ah1, bl[0], bl[1]);
                mma16816(c1[2 * j2], al1, bh[0], bh[1]);
                mma16816(c1[2 * j2 + 1], ah1, bh[2], bh[3]);
                mma16816(c1[2 * j2 + 1], ah1, bl[2], bl[3]);
                mma16816(c1[2 * j2 + 1], al1, bh[2], bh[3]);
            }
            {
                uint32_t bh2[2], bl2[2];
                ldmx2(bh2, bAddr2 + gB);
                ldmx2(bl2, bAddr2 + 20480 + gB);
                mma16816(c0[4], ah0, bh2[0], bh2[1]);
                mma16816(c0[4], ah0, bl2[0], bl2[1]);
                mma16816(c0[4], al0, bh2[0], bh2[1]);
                mma16816(c1[4], ah1, bh2[0], bh2[1]);
                mma16816(c1[4], ah1, bl2[0], bl2[1]);
                mma16816(c1[4], al1, bh2[0], bh2[1]);
            }
        }
    }

    __syncthreads();   // all operand reads done; smem reusable

    // ---- kick basis cp.async into dead operand region (overlaps staging)
    {
        const char* bas = (const char*)(g_basP + (size_t)rt * 128 * BPITCH);
        for (int i = tid; i < 4480; i += 256)
            cp_async16(sb + OFF_BASS + i * 16, bas + i * 16);
        cp_commit();
    }
    cp_wait<1>();        // b3 (group 2) landed; basis still in flight

    // ---- stage C (+b3) to smem [128][SPC]
    float* stg = (float*)(smem + OFF_STGC);
    const float* sB3 = (const float*)(smem + OFF_B3);
    {
        const int rb = mg * 32 + (lane >> 2);
        #pragma unroll
        for (int mtl = 0; mtl < 2; mtl++) {
            int rlo = rb + mtl * 16;
            int rhi = rlo + 8;
            float (*cc)[4] = mtl ? c1 : c0;
            #pragma unroll
            for (int ntl = 0; ntl < 5; ntl++) {
                int col = wn * 40 + ntl * 8 + 2 * (lane & 3);
                float bA = sB3[col], bB = sB3[col + 1];
                stg[rlo * SPC + col]     = cc[ntl][0] + bA;
                stg[rlo * SPC + col + 1] = cc[ntl][1] + bB;
                stg[rhi * SPC + col]     = cc[ntl][2] + bA;
                stg[rhi * SPC + col + 1] = cc[ntl][3] + bB;
            }
        }
    }
    cp_wait<0>();        // basis landed
    __syncthreads();

    // ---- shfl-free warp-per-row einsum epilogue.
    // Lane = (il, ml) = (lane/5, lane%5). Pass p covers cols p*30 + lane.
    // Basis image is [row][ml*28 + d*5 + f] (pitch 140): lane's 25 values
    // load as 7 conflict-free LDS.128 per row, reused across passes.
    const float* bass = (const float*)(smem + OFF_BASS);
    const int ml = lane % 5;
    const int act01 = (lane < 30);
    const int act2  = (lane < 20);

    #pragma unroll 1
    for (int rr = 0; rr < 16; rr++) {
        const int rloc = wid * 16 + rr;
        const float* Rrow = stg + rloc * SPC;
        const float4* bp4 = (const float4*)(bass + rloc * BPITCH + ml * 28);

        float bw[28];
        #pragma unroll
        for (int j = 0; j < 7; j++) {
            float4 v = bp4[j];
            bw[4 * j] = v.x; bw[4 * j + 1] = v.y;
            bw[4 * j + 2] = v.z; bw[4 * j + 3] = v.w;
        }

        float* outR = out + (size_t)(r0 + rloc) * 25600 + (size_t)ob * 800 + h * 80;

        #pragma unroll
        for (int p = 0; p < 3; p++) {
            int col = p * 30 + lane;              // output column
            int act = (p < 2) ? act01 : act2;
            int i5  = (col < 80 ? col - ml : 0);  // i*5 (guard for idle lanes)
            float Rf[5];
            #pragma unroll
            for (int f = 0; f < 5; f++) Rf[f] = Rrow[i5 + f];
            #pragma unroll
            for (int d = 0; d < 5; d++) {
                float a = Rf[0] * bw[d * 5];
                a = fmaf(Rf[1], bw[d * 5 + 1], a);
                a = fmaf(Rf[2], bw[d * 5 + 2], a);
                a = fmaf(Rf[3], bw[d * 5 + 3], a);
                a = fmaf(Rf[4], bw[d * 5 + 4], a);
                if (act) outR[d * 160 + col] = a;
            }
        }
    }
}

extern "C" void kernel_launch(void* const* d_in, const int* in_sizes, int n_in,
                              void* d_out, int out_size)
{
    const float* feat  = (const float*)d_in[0];
    const float* basis = (const float*)d_in[1];
    const float* W1    = (const float*)d_in[2];
    const float* b1    = (const float*)d_in[3];
    const float* g1    = (const float*)d_in[4];
    const float* be1   = (const float*)d_in[5];
    const float* W2    = (const float*)d_in[6];
    const float* b2    = (const float*)d_in[7];
    const float* g2    = (const float*)d_in[8];
    const float* be2   = (const float*)d_in[9];
    const float* W3    = (const float*)d_in[10];
    const float* b3    = (const float*)d_in[11];
    float* out = (float*)d_out;

    cudaFuncSetAttribute(gemm_einsum_mma,
                         cudaFuncAttributeMaxDynamicSharedMemorySize, SMEM_TOTAL);

    prep_kernel<<<416, 256>>>(feat, basis, W1, b1, g1, be1, W2, b2, g2, be2, W3);

    dim3 grid(NOBLK * 2, MTILES);   // (64, 32)
    gemm_einsum_mma<<<grid, 256, SMEM_TOTAL>>>(b3, out);
}